// round 1
// baseline (speedup 1.0000x reference)
#include <cuda_runtime.h>
#include <cuda_bf16.h>
#include <math.h>

// ---------------------------------------------------------------------------
// Problem constants
// ---------------------------------------------------------------------------
#define BATCH 2
#define SEQ 2048
#define HIDDEN 1024
#define NHEAD 16
#define HDIM 64
#define M_TOK (BATCH * SEQ)          // 4096 token rows
#define QKV_N (3 * HIDDEN)           // 3072

// Scratch (allocation-free rule: __device__ globals)
__device__ float g_qkv[(size_t)M_TOK * QKV_N];     // 50.3 MB
__device__ float g_attn[(size_t)M_TOK * HIDDEN];   // 16.8 MB

// ---------------------------------------------------------------------------
// GEMM + bias:  C[M,N] = A[M,K] @ B[K,N] + bias[N]
// BM=BN=128, BK=16, 256 threads, 8x8 register tile per thread.
// All dims are multiples of the tiles for this problem -> no bounds checks.
// ---------------------------------------------------------------------------
__global__ __launch_bounds__(256)
void gemm_bias_kernel(const float* __restrict__ A,
                      const float* __restrict__ B,
                      const float* __restrict__ bias,
                      float* __restrict__ C,
                      int M, int N, int K)
{
    constexpr int BM = 128, BN = 128, BK = 16;
    __shared__ float As[BK][BM + 4];   // A stored transposed: As[k][m]
    __shared__ float Bs[BK][BN];

    const int tid = threadIdx.x;
    const int tn = (tid & 15) * 8;     // 0..120
    const int tm = (tid >> 4) * 8;     // 0..120
    const int brow = blockIdx.y * BM;
    const int bcol = blockIdx.x * BN;

    float acc[8][8];
#pragma unroll
    for (int i = 0; i < 8; i++)
#pragma unroll
        for (int j = 0; j < 8; j++) acc[i][j] = 0.0f;

    for (int k0 = 0; k0 < K; k0 += BK) {
        // --- load A tile (128 x 16) transposed into As ---
#pragma unroll
        for (int it = 0; it < 2; it++) {
            int f = tid + it * 256;          // 0..511 float4 index
            int m = f >> 2;                  // 0..127
            int kk = (f & 3) * 4;            // 0,4,8,12
            float4 v = *(const float4*)(A + (size_t)(brow + m) * K + k0 + kk);
            As[kk + 0][m] = v.x;
            As[kk + 1][m] = v.y;
            As[kk + 2][m] = v.z;
            As[kk + 3][m] = v.w;
        }
        // --- load B tile (16 x 128) ---
#pragma unroll
        for (int it = 0; it < 2; it++) {
            int f = tid + it * 256;          // 0..511
            int kk = f >> 5;                 // 0..15
            int n = (f & 31) * 4;            // 0..124
            *(float4*)&Bs[kk][n] =
                *(const float4*)(B + (size_t)(k0 + kk) * N + bcol + n);
        }
        __syncthreads();

#pragma unroll
        for (int kk = 0; kk < BK; kk++) {
            float a[8], b[8];
            *(float4*)&a[0] = *(float4*)&As[kk][tm];
            *(float4*)&a[4] = *(float4*)&As[kk][tm + 4];
            *(float4*)&b[0] = *(float4*)&Bs[kk][tn];
            *(float4*)&b[4] = *(float4*)&Bs[kk][tn + 4];
#pragma unroll
            for (int i = 0; i < 8; i++)
#pragma unroll
                for (int j = 0; j < 8; j++)
                    acc[i][j] = fmaf(a[i], b[j], acc[i][j]);
        }
        __syncthreads();
    }

    // --- epilogue: add bias, store ---
#pragma unroll
    for (int i = 0; i < 8; i++) {
        size_t row = (size_t)(brow + tm + i);
#pragma unroll
        for (int j = 0; j < 8; j += 4) {
            float4 bv = *(const float4*)(bias + bcol + tn + j);
            float4 o;
            o.x = acc[i][j + 0] + bv.x;
            o.y = acc[i][j + 1] + bv.y;
            o.z = acc[i][j + 2] + bv.z;
            o.w = acc[i][j + 3] + bv.w;
            *(float4*)(C + row * N + bcol + tn + j) = o;
        }
    }
}

// ---------------------------------------------------------------------------
// Flash attention (fp32, causal, NO 1/sqrt(d) scaling).
// Grid: (32 q-blocks, 16 heads, 2 batch). 256 threads.
// Each CTA: 64 q rows x 64 head dim. Thread (tx,ty) owns 4 rows x 4 cols.
// Smem: Qs[64][68] row-major, Kts[64][68] d-major (transposed), Vs[64][68],
//       Ps[64][68]  -> 69632 bytes dynamic.
// ---------------------------------------------------------------------------
#define SROW 68   // padded row stride

__global__ __launch_bounds__(256)
void flash_attn_kernel(const float* __restrict__ qkv, float* __restrict__ out)
{
    extern __shared__ float sm[];
    float* Qs  = sm;                 // [64][68]  Qs[r][d]
    float* Kts = Qs  + 64 * SROW;    // [64][68]  Kts[d][kv]
    float* Vs  = Kts + 64 * SROW;    // [64][68]  Vs[kv][d]
    float* Ps  = Vs  + 64 * SROW;    // [64][68]  Ps[r][kv]

    const int qb = blockIdx.x;       // 0..31
    const int h  = blockIdx.y;       // 0..15
    const int b  = blockIdx.z;       // 0..1

    const int tid = threadIdx.x;
    const int tx = tid & 15;         // 0..15 -> cols
    const int ty = tid >> 4;         // 0..15 -> rows
    const int r0 = ty * 4;
    const int c0 = tx * 4;

    const size_t ld = QKV_N;         // 3072
    const float* qbase = qkv + ((size_t)(b * SEQ + qb * 64)) * ld + h * HDIM;

    // load Q tile: 64 rows x 64 d (1024 float4 total, 4 per thread)
#pragma unroll
    for (int it = 0; it < 4; it++) {
        int idx = tid + it * 256;        // 0..1023
        int r = idx >> 4;
        int dc = (idx & 15) * 4;
        *(float4*)&Qs[r * SROW + dc] =
            *(const float4*)(qbase + (size_t)r * ld + dc);
    }

    float mrow[4], lrow[4], acc[4][4];
#pragma unroll
    for (int i = 0; i < 4; i++) {
        mrow[i] = -1e30f;
        lrow[i] = 0.0f;
#pragma unroll
        for (int j = 0; j < 4; j++) acc[i][j] = 0.0f;
    }
    __syncthreads();

    for (int jb = 0; jb <= qb; jb++) {
        const float* kbase = qkv + ((size_t)(b * SEQ + jb * 64)) * ld + HIDDEN + h * HDIM;
        const float* vbase = kbase + HIDDEN;

        // load K (transposed into Kts[d][kv]) and V (Vs[kv][d])
#pragma unroll
        for (int it = 0; it < 4; it++) {
            int idx = tid + it * 256;
            int kv = idx >> 4;
            int dc = (idx & 15) * 4;
            float4 kl = *(const float4*)(kbase + (size_t)kv * ld + dc);
            Kts[(dc + 0) * SROW + kv] = kl.x;
            Kts[(dc + 1) * SROW + kv] = kl.y;
            Kts[(dc + 2) * SROW + kv] = kl.z;
            Kts[(dc + 3) * SROW + kv] = kl.w;
            *(float4*)&Vs[kv * SROW + dc] =
                *(const float4*)(vbase + (size_t)kv * ld + dc);
        }
        __syncthreads();

        // S = Q @ K^T   (4x4 per thread)
        float s[4][4];
#pragma unroll
        for (int i = 0; i < 4; i++)
#pragma unroll
            for (int j = 0; j < 4; j++) s[i][j] = 0.0f;

#pragma unroll 8
        for (int d = 0; d < HDIM; d++) {
            float4 kv4 = *(float4*)&Kts[d * SROW + c0];
            float q0 = Qs[(r0 + 0) * SROW + d];
            float q1 = Qs[(r0 + 1) * SROW + d];
            float q2 = Qs[(r0 + 2) * SROW + d];
            float q3 = Qs[(r0 + 3) * SROW + d];
            s[0][0] = fmaf(q0, kv4.x, s[0][0]); s[0][1] = fmaf(q0, kv4.y, s[0][1]);
            s[0][2] = fmaf(q0, kv4.z, s[0][2]); s[0][3] = fmaf(q0, kv4.w, s[0][3]);
            s[1][0] = fmaf(q1, kv4.x, s[1][0]); s[1][1] = fmaf(q1, kv4.y, s[1][1]);
            s[1][2] = fmaf(q1, kv4.z, s[1][2]); s[1][3] = fmaf(q1, kv4.w, s[1][3]);
            s[2][0] = fmaf(q2, kv4.x, s[2][0]); s[2][1] = fmaf(q2, kv4.y, s[2][1]);
            s[2][2] = fmaf(q2, kv4.z, s[2][2]); s[2][3] = fmaf(q2, kv4.w, s[2][3]);
            s[3][0] = fmaf(q3, kv4.x, s[3][0]); s[3][1] = fmaf(q3, kv4.y, s[3][1]);
            s[3][2] = fmaf(q3, kv4.z, s[3][2]); s[3][3] = fmaf(q3, kv4.w, s[3][3]);
        }

        // causal mask on the diagonal block
        if (jb == qb) {
#pragma unroll
            for (int i = 0; i < 4; i++)
#pragma unroll
                for (int j = 0; j < 4; j++)
                    if (c0 + j > r0 + i) s[i][j] = -1e30f;
        }

        // online softmax update (row reductions over the 16 tx lanes)
#pragma unroll
        for (int i = 0; i < 4; i++) {
            float mloc = fmaxf(fmaxf(s[i][0], s[i][1]), fmaxf(s[i][2], s[i][3]));
#pragma unroll
            for (int off = 8; off >= 1; off >>= 1)
                mloc = fmaxf(mloc, __shfl_xor_sync(0xffffffffu, mloc, off));
            float mnew = fmaxf(mrow[i], mloc);
            float corr = __expf(mrow[i] - mnew);
            float psum = 0.0f;
#pragma unroll
            for (int j = 0; j < 4; j++) {
                float p = __expf(s[i][j] - mnew);
                s[i][j] = p;
                psum += p;
            }
#pragma unroll
            for (int off = 8; off >= 1; off >>= 1)
                psum += __shfl_xor_sync(0xffffffffu, psum, off);
            lrow[i] = lrow[i] * corr + psum;
            mrow[i] = mnew;
#pragma unroll
            for (int j = 0; j < 4; j++) acc[i][j] *= corr;
        }

        // stage P
#pragma unroll
        for (int i = 0; i < 4; i++) {
            float4 pv = make_float4(s[i][0], s[i][1], s[i][2], s[i][3]);
            *(float4*)&Ps[(r0 + i) * SROW + c0] = pv;
        }
        __syncthreads();

        // O += P @ V
#pragma unroll 8
        for (int kk = 0; kk < 64; kk++) {
            float4 v4 = *(float4*)&Vs[kk * SROW + c0];
            float p0 = Ps[(r0 + 0) * SROW + kk];
            float p1 = Ps[(r0 + 1) * SROW + kk];
            float p2 = Ps[(r0 + 2) * SROW + kk];
            float p3 = Ps[(r0 + 3) * SROW + kk];
            acc[0][0] = fmaf(p0, v4.x, acc[0][0]); acc[0][1] = fmaf(p0, v4.y, acc[0][1]);
            acc[0][2] = fmaf(p0, v4.z, acc[0][2]); acc[0][3] = fmaf(p0, v4.w, acc[0][3]);
            acc[1][0] = fmaf(p1, v4.x, acc[1][0]); acc[1][1] = fmaf(p1, v4.y, acc[1][1]);
            acc[1][2] = fmaf(p1, v4.z, acc[1][2]); acc[1][3] = fmaf(p1, v4.w, acc[1][3]);
            acc[2][0] = fmaf(p2, v4.x, acc[2][0]); acc[2][1] = fmaf(p2, v4.y, acc[2][1]);
            acc[2][2] = fmaf(p2, v4.z, acc[2][2]); acc[2][3] = fmaf(p2, v4.w, acc[2][3]);
            acc[3][0] = fmaf(p3, v4.x, acc[3][0]); acc[3][1] = fmaf(p3, v4.y, acc[3][1]);
            acc[3][2] = fmaf(p3, v4.z, acc[3][2]); acc[3][3] = fmaf(p3, v4.w, acc[3][3]);
        }
        __syncthreads();
    }

    // epilogue: normalize and write [tok, h*64 + c]
#pragma unroll
    for (int i = 0; i < 4; i++) {
        float inv = 1.0f / lrow[i];
        size_t row = (size_t)(b * SEQ + qb * 64 + r0 + i);
        float4 o;
        o.x = acc[i][0] * inv;
        o.y = acc[i][1] * inv;
        o.z = acc[i][2] * inv;
        o.w = acc[i][3] * inv;
        *(float4*)(out + row * HIDDEN + h * HDIM + c0) = o;
    }
}

// ---------------------------------------------------------------------------
// Launch
// ---------------------------------------------------------------------------
extern "C" void kernel_launch(void* const* d_in, const int* in_sizes, int n_in,
                              void* d_out, int out_size)
{
    const float* hidden = (const float*)d_in[0];
    const float* w_attn = (const float*)d_in[1];
    const float* b_attn = (const float*)d_in[2];
    const float* w_proj = (const float*)d_in[3];
    const float* b_proj = (const float*)d_in[4];
    float* out = (float*)d_out;

    float* qkv_ptr = nullptr;
    float* attn_ptr = nullptr;
    cudaGetSymbolAddress((void**)&qkv_ptr, g_qkv);
    cudaGetSymbolAddress((void**)&attn_ptr, g_attn);

    // 1) QKV projection: [4096,1024] @ [1024,3072] + bias
    {
        dim3 grid(QKV_N / 128, M_TOK / 128);
        gemm_bias_kernel<<<grid, 256>>>(hidden, w_attn, b_attn, qkv_ptr,
                                        M_TOK, QKV_N, HIDDEN);
    }

    // 2) flash attention
    {
        const int smem = 4 * 64 * SROW * sizeof(float);  // 69632 B
        cudaFuncSetAttribute(flash_attn_kernel,
                             cudaFuncAttributeMaxDynamicSharedMemorySize, smem);
        dim3 grid(SEQ / 64, NHEAD, BATCH);
        flash_attn_kernel<<<grid, 256, smem>>>(qkv_ptr, attn_ptr);
    }

    // 3) output projection: [4096,1024] @ [1024,1024] + bias
    {
        dim3 grid(HIDDEN / 128, M_TOK / 128);
        gemm_bias_kernel<<<grid, 256>>>(attn_ptr, w_proj, b_proj, out,
                                        M_TOK, HIDDEN, HIDDEN);
    }
}

// round 2
// speedup vs baseline: 1.5191x; 1.5191x over previous
#include <cuda_runtime.h>
#include <cuda_bf16.h>
#include <math.h>
#include <stdint.h>

// ---------------------------------------------------------------------------
// Problem constants
// ---------------------------------------------------------------------------
#define BATCH 2
#define SEQ 2048
#define HIDDEN 1024
#define NHEAD 16
#define HDIM 64
#define M_TOK (BATCH * SEQ)          // 4096 token rows
#define QKV_N (3 * HIDDEN)           // 3072

// Scratch (allocation-free rule: __device__ globals)
__device__ float g_qkv[(size_t)M_TOK * QKV_N];     // 50.3 MB
__device__ float g_attn[(size_t)M_TOK * HIDDEN];   // 16.8 MB

// ---------------------------------------------------------------------------
// TF32 helpers
// ---------------------------------------------------------------------------
__device__ __forceinline__ float f2tf32(float x) {
    uint32_t r;
    asm("cvt.rna.tf32.f32 %0, %1;" : "=r"(r) : "f"(x));
    return __uint_as_float(r);
}

__device__ __forceinline__ void mma_tf32(float c[4], uint32_t a0, uint32_t a1,
                                         uint32_t a2, uint32_t a3,
                                         uint32_t b0, uint32_t b1) {
    asm volatile(
        "mma.sync.aligned.m16n8k8.row.col.f32.tf32.tf32.f32 "
        "{%0,%1,%2,%3}, {%4,%5,%6,%7}, {%8,%9}, {%0,%1,%2,%3};"
        : "+f"(c[0]), "+f"(c[1]), "+f"(c[2]), "+f"(c[3])
        : "r"(a0), "r"(a1), "r"(a2), "r"(a3), "r"(b0), "r"(b1));
}

// ---------------------------------------------------------------------------
// TF32 tensor-core GEMM + bias: C[M,N] = A[M,K] @ B[K,N] + bias[N]
// BM=BN=128, BK=16. 256 threads = 8 warps in 2(M) x 4(N); warp tile 64x32.
// Per warp per k8-step: 4 m-frags x 4 n-frags = 16 mma.m16n8k8.
// Smem: As[m][k] stride 20 (conflict-free frag reads),
//       Bs[k][n] stride 136 (conflict-free frag reads). Double buffered.
// ---------------------------------------------------------------------------
#define ASTR 20
#define BSTR 136

__global__ __launch_bounds__(256)
void gemm_tf32_kernel(const float* __restrict__ A,
                      const float* __restrict__ B,
                      const float* __restrict__ bias,
                      float* __restrict__ C,
                      int M, int N, int K)
{
    constexpr int BM = 128, BN = 128, BK = 16;
    __shared__ float As[2][BM * ASTR];   // [m][k]
    __shared__ float Bs[2][BK * BSTR];   // [k][n]

    const int tid  = threadIdx.x;
    const int warp = tid >> 5;
    const int lane = tid & 31;
    const int wm = (warp >> 2) * 64;     // 0 or 64
    const int wn = (warp & 3) * 32;      // 0..96
    const int tq = lane >> 2;            // 0..7
    const int tr = lane & 3;             // 0..3
    const int brow = blockIdx.y * BM;
    const int bcol = blockIdx.x * BN;

    float acc[4][4][4];
#pragma unroll
    for (int mt = 0; mt < 4; mt++)
#pragma unroll
        for (int nt = 0; nt < 4; nt++)
#pragma unroll
            for (int r = 0; r < 4; r++) acc[mt][nt][r] = 0.0f;

    // gmem tile-load decomposition (per thread: 2 float4 of A, 2 of B)
    const int am[2]  = { (tid + 0)   >> 2, (tid + 256) >> 2 };       // 0..127
    const int ak[2]  = { ((tid + 0)  & 3) * 4, ((tid + 256) & 3) * 4 };
    const int bk[2]  = { (tid + 0)   >> 5, (tid + 256) >> 5 };       // 0..15
    const int bn[2]  = { ((tid + 0)  & 31) * 4, ((tid + 256) & 31) * 4 };

    float4 pa[2], pb[2];

    auto prefetch = [&](int k0) {
#pragma unroll
        for (int it = 0; it < 2; it++) {
            float4 v = *(const float4*)(A + (size_t)(brow + am[it]) * K + k0 + ak[it]);
            v.x = f2tf32(v.x); v.y = f2tf32(v.y);
            v.z = f2tf32(v.z); v.w = f2tf32(v.w);
            pa[it] = v;
            float4 w = *(const float4*)(B + (size_t)(k0 + bk[it]) * N + bcol + bn[it]);
            w.x = f2tf32(w.x); w.y = f2tf32(w.y);
            w.z = f2tf32(w.z); w.w = f2tf32(w.w);
            pb[it] = w;
        }
    };
    auto stage = [&](int buf) {
#pragma unroll
        for (int it = 0; it < 2; it++) {
            *(float4*)&As[buf][am[it] * ASTR + ak[it]] = pa[it];
            *(float4*)&Bs[buf][bk[it] * BSTR + bn[it]] = pb[it];
        }
    };

    prefetch(0);
    stage(0);
    __syncthreads();

    int buf = 0;
    for (int k0 = 0; k0 < K; k0 += BK) {
        const bool has_next = (k0 + BK) < K;
        if (has_next) prefetch(k0 + BK);

        const float* as = As[buf];
        const float* bs = Bs[buf];
#pragma unroll
        for (int ks = 0; ks < 2; ks++) {
            const int kb = ks * 8;
            uint32_t af[4][4];
#pragma unroll
            for (int mt = 0; mt < 4; mt++) {
                const int r0 = wm + mt * 16 + tq;
                af[mt][0] = __float_as_uint(as[(r0 + 0) * ASTR + kb + tr]);
                af[mt][1] = __float_as_uint(as[(r0 + 8) * ASTR + kb + tr]);
                af[mt][2] = __float_as_uint(as[(r0 + 0) * ASTR + kb + tr + 4]);
                af[mt][3] = __float_as_uint(as[(r0 + 8) * ASTR + kb + tr + 4]);
            }
            uint32_t bf[4][2];
#pragma unroll
            for (int nt = 0; nt < 4; nt++) {
                const int c0 = wn + nt * 8 + tq;
                bf[nt][0] = __float_as_uint(bs[(kb + tr + 0) * BSTR + c0]);
                bf[nt][1] = __float_as_uint(bs[(kb + tr + 4) * BSTR + c0]);
            }
#pragma unroll
            for (int mt = 0; mt < 4; mt++)
#pragma unroll
                for (int nt = 0; nt < 4; nt++)
                    mma_tf32(acc[mt][nt], af[mt][0], af[mt][1], af[mt][2], af[mt][3],
                             bf[nt][0], bf[nt][1]);
        }

        if (has_next) {
            stage(buf ^ 1);
            __syncthreads();
            buf ^= 1;
        }
    }

    // epilogue: bias + store (fragment layout: rows tq,+8; cols 2*tr,+1)
#pragma unroll
    for (int nt = 0; nt < 4; nt++) {
        const int col = bcol + wn + nt * 8 + 2 * tr;
        const float2 bv = *(const float2*)(bias + col);
#pragma unroll
        for (int mt = 0; mt < 4; mt++) {
            const int row0 = brow + wm + mt * 16 + tq;
            float2 o0, o1;
            o0.x = acc[mt][nt][0] + bv.x;
            o0.y = acc[mt][nt][1] + bv.y;
            o1.x = acc[mt][nt][2] + bv.x;
            o1.y = acc[mt][nt][3] + bv.y;
            *(float2*)(C + (size_t)row0 * N + col)       = o0;
            *(float2*)(C + (size_t)(row0 + 8) * N + col) = o1;
        }
    }
}

// ---------------------------------------------------------------------------
// Flash attention (fp32, causal, NO 1/sqrt(d) scaling). Unchanged from R1.
// ---------------------------------------------------------------------------
#define SROW 68   // padded row stride

__global__ __launch_bounds__(256)
void flash_attn_kernel(const float* __restrict__ qkv, float* __restrict__ out)
{
    extern __shared__ float sm[];
    float* Qs  = sm;                 // [64][68]  Qs[r][d]
    float* Kts = Qs  + 64 * SROW;    // [64][68]  Kts[d][kv]
    float* Vs  = Kts + 64 * SROW;    // [64][68]  Vs[kv][d]
    float* Ps  = Vs  + 64 * SROW;    // [64][68]  Ps[r][kv]

    const int qb = blockIdx.x;
    const int h  = blockIdx.y;
    const int b  = blockIdx.z;

    const int tid = threadIdx.x;
    const int tx = tid & 15;
    const int ty = tid >> 4;
    const int r0 = ty * 4;
    const int c0 = tx * 4;

    const size_t ld = QKV_N;
    const float* qbase = qkv + ((size_t)(b * SEQ + qb * 64)) * ld + h * HDIM;

#pragma unroll
    for (int it = 0; it < 4; it++) {
        int idx = tid + it * 256;
        int r = idx >> 4;
        int dc = (idx & 15) * 4;
        *(float4*)&Qs[r * SROW + dc] =
            *(const float4*)(qbase + (size_t)r * ld + dc);
    }

    float mrow[4], lrow[4], acc[4][4];
#pragma unroll
    for (int i = 0; i < 4; i++) {
        mrow[i] = -1e30f;
        lrow[i] = 0.0f;
#pragma unroll
        for (int j = 0; j < 4; j++) acc[i][j] = 0.0f;
    }
    __syncthreads();

    for (int jb = 0; jb <= qb; jb++) {
        const float* kbase = qkv + ((size_t)(b * SEQ + jb * 64)) * ld + HIDDEN + h * HDIM;
        const float* vbase = kbase + HIDDEN;

#pragma unroll
        for (int it = 0; it < 4; it++) {
            int idx = tid + it * 256;
            int kv = idx >> 4;
            int dc = (idx & 15) * 4;
            float4 kl = *(const float4*)(kbase + (size_t)kv * ld + dc);
            Kts[(dc + 0) * SROW + kv] = kl.x;
            Kts[(dc + 1) * SROW + kv] = kl.y;
            Kts[(dc + 2) * SROW + kv] = kl.z;
            Kts[(dc + 3) * SROW + kv] = kl.w;
            *(float4*)&Vs[kv * SROW + dc] =
                *(const float4*)(vbase + (size_t)kv * ld + dc);
        }
        __syncthreads();

        float s[4][4];
#pragma unroll
        for (int i = 0; i < 4; i++)
#pragma unroll
            for (int j = 0; j < 4; j++) s[i][j] = 0.0f;

#pragma unroll 8
        for (int d = 0; d < HDIM; d++) {
            float4 kv4 = *(float4*)&Kts[d * SROW + c0];
            float q0 = Qs[(r0 + 0) * SROW + d];
            float q1 = Qs[(r0 + 1) * SROW + d];
            float q2 = Qs[(r0 + 2) * SROW + d];
            float q3 = Qs[(r0 + 3) * SROW + d];
            s[0][0] = fmaf(q0, kv4.x, s[0][0]); s[0][1] = fmaf(q0, kv4.y, s[0][1]);
            s[0][2] = fmaf(q0, kv4.z, s[0][2]); s[0][3] = fmaf(q0, kv4.w, s[0][3]);
            s[1][0] = fmaf(q1, kv4.x, s[1][0]); s[1][1] = fmaf(q1, kv4.y, s[1][1]);
            s[1][2] = fmaf(q1, kv4.z, s[1][2]); s[1][3] = fmaf(q1, kv4.w, s[1][3]);
            s[2][0] = fmaf(q2, kv4.x, s[2][0]); s[2][1] = fmaf(q2, kv4.y, s[2][1]);
            s[2][2] = fmaf(q2, kv4.z, s[2][2]); s[2][3] = fmaf(q2, kv4.w, s[2][3]);
            s[3][0] = fmaf(q3, kv4.x, s[3][0]); s[3][1] = fmaf(q3, kv4.y, s[3][1]);
            s[3][2] = fmaf(q3, kv4.z, s[3][2]); s[3][3] = fmaf(q3, kv4.w, s[3][3]);
        }

        if (jb == qb) {
#pragma unroll
            for (int i = 0; i < 4; i++)
#pragma unroll
                for (int j = 0; j < 4; j++)
                    if (c0 + j > r0 + i) s[i][j] = -1e30f;
        }

#pragma unroll
        for (int i = 0; i < 4; i++) {
            float mloc = fmaxf(fmaxf(s[i][0], s[i][1]), fmaxf(s[i][2], s[i][3]));
#pragma unroll
            for (int off = 8; off >= 1; off >>= 1)
                mloc = fmaxf(mloc, __shfl_xor_sync(0xffffffffu, mloc, off));
            float mnew = fmaxf(mrow[i], mloc);
            float corr = __expf(mrow[i] - mnew);
            float psum = 0.0f;
#pragma unroll
            for (int j = 0; j < 4; j++) {
                float p = __expf(s[i][j] - mnew);
                s[i][j] = p;
                psum += p;
            }
#pragma unroll
            for (int off = 8; off >= 1; off >>= 1)
                psum += __shfl_xor_sync(0xffffffffu, psum, off);
            lrow[i] = lrow[i] * corr + psum;
            mrow[i] = mnew;
#pragma unroll
            for (int j = 0; j < 4; j++) acc[i][j] *= corr;
        }

#pragma unroll
        for (int i = 0; i < 4; i++) {
            float4 pv = make_float4(s[i][0], s[i][1], s[i][2], s[i][3]);
            *(float4*)&Ps[(r0 + i) * SROW + c0] = pv;
        }
        __syncthreads();

#pragma unroll 8
        for (int kk = 0; kk < 64; kk++) {
            float4 v4 = *(float4*)&Vs[kk * SROW + c0];
            float p0 = Ps[(r0 + 0) * SROW + kk];
            float p1 = Ps[(r0 + 1) * SROW + kk];
            float p2 = Ps[(r0 + 2) * SROW + kk];
            float p3 = Ps[(r0 + 3) * SROW + kk];
            acc[0][0] = fmaf(p0, v4.x, acc[0][0]); acc[0][1] = fmaf(p0, v4.y, acc[0][1]);
            acc[0][2] = fmaf(p0, v4.z, acc[0][2]); acc[0][3] = fmaf(p0, v4.w, acc[0][3]);
            acc[1][0] = fmaf(p1, v4.x, acc[1][0]); acc[1][1] = fmaf(p1, v4.y, acc[1][1]);
            acc[1][2] = fmaf(p1, v4.z, acc[1][2]); acc[1][3] = fmaf(p1, v4.w, acc[1][3]);
            acc[2][0] = fmaf(p2, v4.x, acc[2][0]); acc[2][1] = fmaf(p2, v4.y, acc[2][1]);
            acc[2][2] = fmaf(p2, v4.z, acc[2][2]); acc[2][3] = fmaf(p2, v4.w, acc[2][3]);
            acc[3][0] = fmaf(p3, v4.x, acc[3][0]); acc[3][1] = fmaf(p3, v4.y, acc[3][1]);
            acc[3][2] = fmaf(p3, v4.z, acc[3][2]); acc[3][3] = fmaf(p3, v4.w, acc[3][3]);
        }
        __syncthreads();
    }

#pragma unroll
    for (int i = 0; i < 4; i++) {
        float inv = 1.0f / lrow[i];
        size_t row = (size_t)(b * SEQ + qb * 64 + r0 + i);
        float4 o;
        o.x = acc[i][0] * inv;
        o.y = acc[i][1] * inv;
        o.z = acc[i][2] * inv;
        o.w = acc[i][3] * inv;
        *(float4*)(out + row * HIDDEN + h * HDIM + c0) = o;
    }
}

// ---------------------------------------------------------------------------
// Launch
// ---------------------------------------------------------------------------
extern "C" void kernel_launch(void* const* d_in, const int* in_sizes, int n_in,
                              void* d_out, int out_size)
{
    const float* hidden = (const float*)d_in[0];
    const float* w_attn = (const float*)d_in[1];
    const float* b_attn = (const float*)d_in[2];
    const float* w_proj = (const float*)d_in[3];
    const float* b_proj = (const float*)d_in[4];
    float* out = (float*)d_out;

    float* qkv_ptr = nullptr;
    float* attn_ptr = nullptr;
    cudaGetSymbolAddress((void**)&qkv_ptr, g_qkv);
    cudaGetSymbolAddress((void**)&attn_ptr, g_attn);

    // 1) QKV projection: [4096,1024] @ [1024,3072] + bias (tf32 tensor cores)
    {
        dim3 grid(QKV_N / 128, M_TOK / 128);
        gemm_tf32_kernel<<<grid, 256>>>(hidden, w_attn, b_attn, qkv_ptr,
                                        M_TOK, QKV_N, HIDDEN);
    }

    // 2) flash attention
    {
        const int smem = 4 * 64 * SROW * sizeof(float);  // 69632 B
        cudaFuncSetAttribute(flash_attn_kernel,
                             cudaFuncAttributeMaxDynamicSharedMemorySize, smem);
        dim3 grid(SEQ / 64, NHEAD, BATCH);
        flash_attn_kernel<<<grid, 256, smem>>>(qkv_ptr, attn_ptr);
    }

    // 3) output projection: [4096,1024] @ [1024,1024] + bias (tf32 tensor cores)
    {
        dim3 grid(HIDDEN / 128, M_TOK / 128);
        gemm_tf32_kernel<<<grid, 256>>>(attn_ptr, w_proj, b_proj, out,
                                        M_TOK, HIDDEN, HIDDEN);
    }
}

// round 3
// speedup vs baseline: 2.4193x; 1.5926x over previous
#include <cuda_runtime.h>
#include <cuda_bf16.h>
#include <math.h>
#include <stdint.h>

// ---------------------------------------------------------------------------
// Problem constants
// ---------------------------------------------------------------------------
#define BATCH 2
#define SEQ 2048
#define HIDDEN 1024
#define NHEAD 16
#define HDIM 64
#define M_TOK (BATCH * SEQ)          // 4096
#define QKV_N (3 * HIDDEN)           // 3072
#define LD32 (QKV_N / 2)             // 1536 u32 per token row in split planes

// Scratch (__device__ globals per allocation rules)
__device__ uint32_t g_qh[(size_t)M_TOK * LD32];   // qkv hi plane (bf16 pairs)
__device__ uint32_t g_ql[(size_t)M_TOK * LD32];   // qkv lo plane
__device__ float    g_attn[(size_t)M_TOK * HIDDEN];

// ---------------------------------------------------------------------------
// Helpers
// ---------------------------------------------------------------------------
__device__ __forceinline__ void mma_bf16(float* c, uint32_t a0, uint32_t a1,
                                         uint32_t a2, uint32_t a3,
                                         uint32_t b0, uint32_t b1) {
    asm volatile(
        "mma.sync.aligned.m16n8k16.row.col.f32.bf16.bf16.f32 "
        "{%0,%1,%2,%3}, {%4,%5,%6,%7}, {%8,%9}, {%0,%1,%2,%3};"
        : "+f"(c[0]), "+f"(c[1]), "+f"(c[2]), "+f"(c[3])
        : "r"(a0), "r"(a1), "r"(a2), "r"(a3), "r"(b0), "r"(b1));
}

// split two fp32 into bf16 hi-pair and lo-pair (low 16 bits = first element)
__device__ __forceinline__ void split2(float x, float y,
                                       uint32_t& hi, uint32_t& lo) {
    __nv_bfloat162 h = __floats2bfloat162_rn(x, y);
    float2 hf = __bfloat1622float2(h);
    __nv_bfloat162 l = __floats2bfloat162_rn(x - hf.x, y - hf.y);
    hi = *reinterpret_cast<uint32_t*>(&h);
    lo = *reinterpret_cast<uint32_t*>(&l);
}

// ---------------------------------------------------------------------------
// bf16x3 GEMM + bias:  C = A[M,K] @ B[K,N] + bias
// BM=BN=128, BK=16 (one mma k-step), 256 thr = 8 warps (2m x 4n), warp 64x32.
// Per warp per k-step: 4mt x 4nt x 3 = 48 mma.
// mode 0: store fp32 C. mode 1: store split bf16 planes Chi/Clo (u32 pairs).
// ---------------------------------------------------------------------------
#define GASTR 12    // u32 stride of A smem plane [m][kp]
#define GBSTR 136   // u32 stride of B smem plane [kp][n]

__global__ __launch_bounds__(256)
void gemm_bf16x3(const float* __restrict__ A, const float* __restrict__ B,
                 const float* __restrict__ bias,
                 float* __restrict__ Cf,
                 uint32_t* __restrict__ Chi, uint32_t* __restrict__ Clo,
                 int M, int N, int K, int mode)
{
    __shared__ uint32_t Ah[2][128 * GASTR], Al[2][128 * GASTR];
    __shared__ uint32_t Bh[2][8 * GBSTR],  Bl[2][8 * GBSTR];

    const int tid  = threadIdx.x;
    const int warp = tid >> 5;
    const int lane = tid & 31;
    const int g = lane >> 2;            // 0..7
    const int t = lane & 3;             // 0..3
    const int wm = (warp >> 2) * 64;
    const int wn = (warp & 3) * 32;
    const int brow = blockIdx.y * 128;
    const int bcol = blockIdx.x * 128;

    float acc[4][4][4];
#pragma unroll
    for (int mt = 0; mt < 4; mt++)
#pragma unroll
        for (int nt = 0; nt < 4; nt++)
#pragma unroll
            for (int r = 0; r < 4; r++) acc[mt][nt][r] = 0.0f;

    // A: 2 float4 per thread; B: 1 task = 2 float4 (rows 2kp, 2kp+1)
    const int am[2] = { (tid + 0) >> 2, (tid + 256) >> 2 };
    const int aq[2] = { (tid + 0) & 3,  (tid + 256) & 3 };
    const int bkp   = tid >> 5;              // 0..7
    const int bn0   = (tid & 31) * 4;

    float4 pa[2], pb0, pb1;

    auto prefetch = [&](int k0) {
#pragma unroll
        for (int it = 0; it < 2; it++)
            pa[it] = *(const float4*)(A + (size_t)(brow + am[it]) * K + k0 + aq[it] * 4);
        pb0 = *(const float4*)(B + (size_t)(k0 + 2 * bkp) * N + bcol + bn0);
        pb1 = *(const float4*)(B + (size_t)(k0 + 2 * bkp + 1) * N + bcol + bn0);
    };
    auto stage = [&](int buf) {
#pragma unroll
        for (int it = 0; it < 2; it++) {
            uint32_t h0, l0, h1, l1;
            split2(pa[it].x, pa[it].y, h0, l0);
            split2(pa[it].z, pa[it].w, h1, l1);
            int base = am[it] * GASTR + aq[it] * 2;
            Ah[buf][base] = h0;  Ah[buf][base + 1] = h1;
            Al[buf][base] = l0;  Al[buf][base + 1] = l1;
        }
        // B pairs along k: (row 2kp, row 2kp+1)
        uint32_t h[4], l[4];
        split2(pb0.x, pb1.x, h[0], l[0]);
        split2(pb0.y, pb1.y, h[1], l[1]);
        split2(pb0.z, pb1.z, h[2], l[2]);
        split2(pb0.w, pb1.w, h[3], l[3]);
        *(uint4*)&Bh[buf][bkp * GBSTR + bn0] = make_uint4(h[0], h[1], h[2], h[3]);
        *(uint4*)&Bl[buf][bkp * GBSTR + bn0] = make_uint4(l[0], l[1], l[2], l[3]);
    };

    prefetch(0);
    stage(0);
    __syncthreads();

    int buf = 0;
    for (int k0 = 0; k0 < K; k0 += 16) {
        const bool has_next = (k0 + 16) < K;
        if (has_next) prefetch(k0 + 16);

        // B fragments (cached for all mt)
        uint32_t bh[4][2], bl[4][2];
#pragma unroll
        for (int nt = 0; nt < 4; nt++) {
            const int col = wn + nt * 8 + g;
            bh[nt][0] = Bh[buf][t * GBSTR + col];
            bh[nt][1] = Bh[buf][(t + 4) * GBSTR + col];
            bl[nt][0] = Bl[buf][t * GBSTR + col];
            bl[nt][1] = Bl[buf][(t + 4) * GBSTR + col];
        }
#pragma unroll
        for (int mt = 0; mt < 4; mt++) {
            const int r = wm + mt * 16 + g;
            uint32_t ah0 = Ah[buf][r * GASTR + t];
            uint32_t ah1 = Ah[buf][(r + 8) * GASTR + t];
            uint32_t ah2 = Ah[buf][r * GASTR + t + 4];
            uint32_t ah3 = Ah[buf][(r + 8) * GASTR + t + 4];
            uint32_t al0 = Al[buf][r * GASTR + t];
            uint32_t al1 = Al[buf][(r + 8) * GASTR + t];
            uint32_t al2 = Al[buf][r * GASTR + t + 4];
            uint32_t al3 = Al[buf][(r + 8) * GASTR + t + 4];
#pragma unroll
            for (int nt = 0; nt < 4; nt++) {
                mma_bf16(acc[mt][nt], ah0, ah1, ah2, ah3, bh[nt][0], bh[nt][1]);
                mma_bf16(acc[mt][nt], ah0, ah1, ah2, ah3, bl[nt][0], bl[nt][1]);
                mma_bf16(acc[mt][nt], al0, al1, al2, al3, bh[nt][0], bh[nt][1]);
            }
        }

        if (has_next) {
            stage(buf ^ 1);
            __syncthreads();
            buf ^= 1;
        }
    }

    // epilogue: c-frag rows g,g+8; cols 2t,2t+1
#pragma unroll
    for (int nt = 0; nt < 4; nt++) {
        const int col = bcol + wn + nt * 8 + 2 * t;
        const float2 bv = *(const float2*)(bias + col);
#pragma unroll
        for (int mt = 0; mt < 4; mt++) {
            const int row0 = brow + wm + mt * 16 + g;
            float v00 = acc[mt][nt][0] + bv.x, v01 = acc[mt][nt][1] + bv.y;
            float v10 = acc[mt][nt][2] + bv.x, v11 = acc[mt][nt][3] + bv.y;
            if (mode == 0) {
                *(float2*)(Cf + (size_t)row0 * N + col)       = make_float2(v00, v01);
                *(float2*)(Cf + (size_t)(row0 + 8) * N + col) = make_float2(v10, v11);
            } else {
                uint32_t h, l;
                size_t i0 = ((size_t)row0 * N + col) >> 1;
                split2(v00, v01, h, l);  Chi[i0] = h;  Clo[i0] = l;
                size_t i1 = ((size_t)(row0 + 8) * N + col) >> 1;
                split2(v10, v11, h, l);  Chi[i1] = h;  Clo[i1] = l;
            }
        }
    }
}

// ---------------------------------------------------------------------------
// Tensor-core flash attention, bf16x3, causal, NO 1/sqrt(d) scaling.
// CTA: 128 q-rows x one head. 8 warps x m16. kv blocks of 64.
// K kept in natural [tok][d-pair] layout (direct B-frag reads for QK^T).
// V transposed into [kv-pair][d] via byte_perm. P stays in registers.
// ---------------------------------------------------------------------------
#define KSTR 36   // Ks [64 tok][32 dp] u32 stride
#define VSTR 72   // Vs [32 kvp][64 d] u32 stride

__global__ __launch_bounds__(256)
void flash_bf16x3(const uint32_t* __restrict__ qh,
                  const uint32_t* __restrict__ ql,
                  float* __restrict__ out)
{
    __shared__ uint32_t Ksh[64 * KSTR], Ksl[64 * KSTR];
    __shared__ uint32_t Vsh[32 * VSTR], Vsl[32 * VSTR];

    const int qbx = blockIdx.x;          // 0..15 (128 rows each)
    const int h   = blockIdx.y;
    const int b   = blockIdx.z;

    const int tid  = threadIdx.x;
    const int wid  = tid >> 5;
    const int lane = tid & 31;
    const int g = lane >> 2;
    const int t = lane & 3;

    const int qoff = h * 32;
    const int koff = 512 + h * 32;
    const int voff = 1024 + h * 32;

    const int wq = qbx * 128 + wid * 16;           // warp's first q row (seq)
    const size_t rowA = (size_t)(b * SEQ + wq + g) * LD32;
    const size_t rowB = rowA + 8 * LD32;

    // Q fragments held in registers for the whole CTA lifetime
    uint32_t qfh[4][4], qfl[4][4];
#pragma unroll
    for (int s = 0; s < 4; s++) {
        qfh[s][0] = qh[rowA + qoff + s * 8 + t];
        qfh[s][1] = qh[rowB + qoff + s * 8 + t];
        qfh[s][2] = qh[rowA + qoff + s * 8 + t + 4];
        qfh[s][3] = qh[rowB + qoff + s * 8 + t + 4];
        qfl[s][0] = ql[rowA + qoff + s * 8 + t];
        qfl[s][1] = ql[rowB + qoff + s * 8 + t];
        qfl[s][2] = ql[rowA + qoff + s * 8 + t + 4];
        qfl[s][3] = ql[rowB + qoff + s * 8 + t + 4];
    }

    float oa[8][4];
#pragma unroll
    for (int nt = 0; nt < 8; nt++)
#pragma unroll
        for (int r = 0; r < 4; r++) oa[nt][r] = 0.0f;
    float m0 = -1e30f, m1 = -1e30f, l0 = 0.0f, l1 = 0.0f;

    const int r0g = wq + g;        // global seq rows this thread owns
    const int r1g = wq + g + 8;
    const int nblocks = 2 * qbx + 2;

    for (int jb = 0; jb < nblocks; jb++) {
        __syncthreads();
        // --- stage K: [tok][dp] natural layout ---
#pragma unroll
        for (int i = 0; i < 8; i++) {
            int idx = tid + i * 256;
            int tok = idx >> 5, dp = idx & 31;
            size_t gi = (size_t)(b * SEQ + jb * 64 + tok) * LD32 + koff + dp;
            Ksh[tok * KSTR + dp] = qh[gi];
            Ksl[tok * KSTR + dp] = ql[gi];
        }
        // --- stage V: transpose to [kvp][d] pairs along kv ---
#pragma unroll
        for (int i = 0; i < 4; i++) {
            int idx = tid + i * 256;
            int r = idx >> 5, j = idx & 31;
            size_t g0 = (size_t)(b * SEQ + jb * 64 + 2 * r) * LD32 + voff + j;
            uint32_t a0 = qh[g0], b0 = qh[g0 + LD32];
            Vsh[r * VSTR + 2 * j]     = __byte_perm(a0, b0, 0x5410);
            Vsh[r * VSTR + 2 * j + 1] = __byte_perm(a0, b0, 0x7632);
            uint32_t a1 = ql[g0], b1 = ql[g0 + LD32];
            Vsl[r * VSTR + 2 * j]     = __byte_perm(a1, b1, 0x5410);
            Vsl[r * VSTR + 2 * j + 1] = __byte_perm(a1, b1, 0x7632);
        }
        __syncthreads();

        if (jb * 64 > wq + 15) continue;   // fully masked for this warp

        // --- S = Q K^T ---
        float sc[8][4];
#pragma unroll
        for (int nt = 0; nt < 8; nt++)
#pragma unroll
            for (int r = 0; r < 4; r++) sc[nt][r] = 0.0f;

#pragma unroll
        for (int s = 0; s < 4; s++) {
#pragma unroll
            for (int nt = 0; nt < 8; nt++) {
                const int tok = nt * 8 + g;
                uint32_t kh0 = Ksh[tok * KSTR + s * 8 + t];
                uint32_t kh1 = Ksh[tok * KSTR + s * 8 + t + 4];
                uint32_t kl0 = Ksl[tok * KSTR + s * 8 + t];
                uint32_t kl1 = Ksl[tok * KSTR + s * 8 + t + 4];
                mma_bf16(sc[nt], qfh[s][0], qfh[s][1], qfh[s][2], qfh[s][3], kh0, kh1);
                mma_bf16(sc[nt], qfh[s][0], qfh[s][1], qfh[s][2], qfh[s][3], kl0, kl1);
                mma_bf16(sc[nt], qfl[s][0], qfl[s][1], qfl[s][2], qfl[s][3], kh0, kh1);
            }
        }

        // --- causal mask (diagonal-crossing blocks only) ---
        if (jb * 64 + 63 > wq) {
#pragma unroll
            for (int nt = 0; nt < 8; nt++) {
                int c = jb * 64 + nt * 8 + 2 * t;
                if (c > r0g)     sc[nt][0] = -1e30f;
                if (c + 1 > r0g) sc[nt][1] = -1e30f;
                if (c > r1g)     sc[nt][2] = -1e30f;
                if (c + 1 > r1g) sc[nt][3] = -1e30f;
            }
        }

        // --- online softmax (rows g and g+8; reduce over quad lanes) ---
        float mx0 = -1e30f, mx1 = -1e30f;
#pragma unroll
        for (int nt = 0; nt < 8; nt++) {
            mx0 = fmaxf(mx0, fmaxf(sc[nt][0], sc[nt][1]));
            mx1 = fmaxf(mx1, fmaxf(sc[nt][2], sc[nt][3]));
        }
#pragma unroll
        for (int off = 1; off <= 2; off <<= 1) {
            mx0 = fmaxf(mx0, __shfl_xor_sync(0xffffffffu, mx0, off));
            mx1 = fmaxf(mx1, __shfl_xor_sync(0xffffffffu, mx1, off));
        }
        float mn0 = fmaxf(m0, mx0), mn1 = fmaxf(m1, mx1);
        float corr0 = __expf(m0 - mn0), corr1 = __expf(m1 - mn1);
        float s0 = 0.0f, s1 = 0.0f;
#pragma unroll
        for (int nt = 0; nt < 8; nt++) {
            sc[nt][0] = __expf(sc[nt][0] - mn0);
            sc[nt][1] = __expf(sc[nt][1] - mn0);
            sc[nt][2] = __expf(sc[nt][2] - mn1);
            sc[nt][3] = __expf(sc[nt][3] - mn1);
            s0 += sc[nt][0] + sc[nt][1];
            s1 += sc[nt][2] + sc[nt][3];
        }
#pragma unroll
        for (int off = 1; off <= 2; off <<= 1) {
            s0 += __shfl_xor_sync(0xffffffffu, s0, off);
            s1 += __shfl_xor_sync(0xffffffffu, s1, off);
        }
        l0 = l0 * corr0 + s0;  m0 = mn0;
        l1 = l1 * corr1 + s1;  m1 = mn1;
#pragma unroll
        for (int nt = 0; nt < 8; nt++) {
            oa[nt][0] *= corr0;  oa[nt][1] *= corr0;
            oa[nt][2] *= corr1;  oa[nt][3] *= corr1;
        }

        // --- O += P V  (P a-frags built from sc registers) ---
#pragma unroll
        for (int s = 0; s < 4; s++) {
            uint32_t ph[4], pl[4];
            split2(sc[2 * s][0],     sc[2 * s][1],     ph[0], pl[0]);
            split2(sc[2 * s][2],     sc[2 * s][3],     ph[1], pl[1]);
            split2(sc[2 * s + 1][0], sc[2 * s + 1][1], ph[2], pl[2]);
            split2(sc[2 * s + 1][2], sc[2 * s + 1][3], ph[3], pl[3]);
#pragma unroll
            for (int nt = 0; nt < 8; nt++) {
                const int d = nt * 8 + g;
                uint32_t vh0 = Vsh[(s * 8 + t) * VSTR + d];
                uint32_t vh1 = Vsh[(s * 8 + t + 4) * VSTR + d];
                uint32_t vl0 = Vsl[(s * 8 + t) * VSTR + d];
                uint32_t vl1 = Vsl[(s * 8 + t + 4) * VSTR + d];
                mma_bf16(oa[nt], ph[0], ph[1], ph[2], ph[3], vh0, vh1);
                mma_bf16(oa[nt], ph[0], ph[1], ph[2], ph[3], vl0, vl1);
                mma_bf16(oa[nt], pl[0], pl[1], pl[2], pl[3], vh0, vh1);
            }
        }
    }

    // --- epilogue ---
    const float inv0 = 1.0f / l0, inv1 = 1.0f / l1;
    const size_t orow0 = (size_t)(b * SEQ + r0g) * HIDDEN + h * HDIM;
    const size_t orow1 = (size_t)(b * SEQ + r1g) * HIDDEN + h * HDIM;
#pragma unroll
    for (int nt = 0; nt < 8; nt++) {
        const int d = nt * 8 + 2 * t;
        *(float2*)(out + orow0 + d) = make_float2(oa[nt][0] * inv0, oa[nt][1] * inv0);
        *(float2*)(out + orow1 + d) = make_float2(oa[nt][2] * inv1, oa[nt][3] * inv1);
    }
}

// ---------------------------------------------------------------------------
// Launch
// ---------------------------------------------------------------------------
extern "C" void kernel_launch(void* const* d_in, const int* in_sizes, int n_in,
                              void* d_out, int out_size)
{
    const float* hidden = (const float*)d_in[0];
    const float* w_attn = (const float*)d_in[1];
    const float* b_attn = (const float*)d_in[2];
    const float* w_proj = (const float*)d_in[3];
    const float* b_proj = (const float*)d_in[4];
    float* out = (float*)d_out;

    uint32_t *qh = nullptr, *ql = nullptr;
    float* attn = nullptr;
    cudaGetSymbolAddress((void**)&qh, g_qh);
    cudaGetSymbolAddress((void**)&ql, g_ql);
    cudaGetSymbolAddress((void**)&attn, g_attn);

    // 1) QKV projection -> split bf16 hi/lo planes
    {
        dim3 grid(QKV_N / 128, M_TOK / 128);
        gemm_bf16x3<<<grid, 256>>>(hidden, w_attn, b_attn,
                                   nullptr, qh, ql,
                                   M_TOK, QKV_N, HIDDEN, 1);
    }
    // 2) flash attention (tensor cores, bf16x3)
    {
        dim3 grid(SEQ / 128, NHEAD, BATCH);
        flash_bf16x3<<<grid, 256>>>(qh, ql, attn);
    }
    // 3) output projection -> fp32
    {
        dim3 grid(HIDDEN / 128, M_TOK / 128);
        gemm_bf16x3<<<grid, 256>>>(attn, w_proj, b_proj,
                                   out, nullptr, nullptr,
                                   M_TOK, HIDDEN, HIDDEN, 0);
    }
}